// round 16
// baseline (speedup 1.0000x reference)
#include <cuda_runtime.h>
#include <math.h>
#include <stdint.h>

// ---------------- problem constants ----------------
#define BSZ   4
#define CHN   28
#define HH    240
#define WW    320
#define NPIX  (HH*WW)
#define VRN   100
#define ZN    80
#define ZAG0  11
#define ZAG1  49
#define ZAGN  (ZAG1-ZAG0)  // 38
#define NSEG  24
#define NQD   6
#define NF    28
#define MC    480
#define MC2   (MC*MC)
#define PROJ_ROWS 96
#define FP_SIZE  (BSZ*VRN*VRN)
#define MAP_SIZE (BSZ*CHN*MC2)
#define POSE_OFF (FP_SIZE + MAP_SIZE)
#define NXY   (BSZ*VRN*VRN)

#define DEG2RAD_F 0.017453292519943295f
#define R2D_F     57.29577951308232f

// ---------------- scratch ----------------
// Invariant: all-zero at kernel_launch entry. .bss zero at module load; each
// launch re-zeros at its TAIL (overlapped with B).
__device__ float g_vox0[(size_t)NXY*ZN];                        // 12.8 MB  [xy][z]
__device__ float g_voxs[(size_t)NXY*NQD*ZAGN*4];                // 145.9 MB [xy][q][z][4]
__device__ float g_proj[BSZ*PROJ_ROWS*VRN*NF];                  // 4.3 MB

__device__ __forceinline__ float clip01(float v) { return fminf(fmaxf(v, 0.0f), 1.0f); }

__device__ __forceinline__ float getc(float4 v, int k) {
    switch (k & 3) {
        case 0: return v.x;
        case 1: return v.y;
        case 2: return v.z;
        default: return v.w;
    }
}

// ---------------- zero scratch (TAIL, overlapped with kernel B) ----------------
__global__ void zero_vox_kernel() {
    const size_t n0 = (size_t)NXY*ZN / 4;
    const size_t n1 = (size_t)NXY*NQD*ZAGN*4 / 4;
    size_t i = (size_t)blockIdx.x * blockDim.x + threadIdx.x;
    size_t stride = (size_t)gridDim.x * blockDim.x;
    float4 z4 = make_float4(0.f,0.f,0.f,0.f);
    float4* p0 = (float4*)g_vox0;
    float4* p1 = (float4*)g_voxs;
    for (size_t k = i; k < n0; k += stride) p0[k] = z4;
    for (size_t k = i; k < n1; k += stride) p1[k] = z4;
}

// ---------------- trilinear splat ----------------
__global__ void __launch_bounds__(256) splat_kernel(const float* __restrict__ obs,
                                                    const float* __restrict__ view_angles) {
    int pid = blockIdx.x * blockDim.x + threadIdx.x;
    if (pid >= BSZ * NPIX) return;
    int b = pid / NPIX;
    int r = pid - b * NPIX;
    int i = r / WW;
    int j = r - i * WW;

    const float* ob = obs + (size_t)b * CHN * NPIX;
    float d = __ldg(ob + 3 * NPIX + r);
    if (d < 0.0f) d = 10000.0f;

    const float FOCAL = (float)(160.0 / 0.5773502691896257);
    float X = ((float)j - 159.5f) * d / FOCAL;
    float Z = ((float)(239 - i) - 119.5f) * d / FOCAL;
    float Y = d;

    float a  = view_angles[b] * DEG2RAD_F;
    float ca = cosf(a), sa = sinf(a);
    float Xr = X + 250.0f;
    float Yr = ca * Y - sa * Z;
    float Zr = sa * Y + ca * Z + 155.0f;

    float xn = (Xr / 5.0f - 50.0f) / 100.0f * 2.0f;
    float yn = (Yr / 5.0f - 50.0f) / 100.0f * 2.0f;
    float zn = (Zr / 5.0f - 32.0f) / 80.0f  * 2.0f;
    float pos0 = xn * 50.0f + 50.0f;
    float pos1 = yn * 50.0f + 50.0f;
    float pos2 = zn * 40.0f + 40.0f;

    float p0v[2], w0v[2], p1v[2], w1v[2], p2v[2], w2v[2];
    {
        float fl = floorf(pos0);
        #pragma unroll
        for (int o = 0; o < 2; o++) {
            float p = fl + (float)o;
            bool s = (p > 0.0f) && (p < 100.0f);
            w0v[o] = s ? (1.0f - fabsf(pos0 - p)) : 0.0f;
            p0v[o] = s ? p : 0.0f;
        }
    }
    {
        float fl = floorf(pos1);
        #pragma unroll
        for (int o = 0; o < 2; o++) {
            float p = fl + (float)o;
            bool s = (p > 0.0f) && (p < 100.0f);
            w1v[o] = s ? (1.0f - fabsf(pos1 - p)) : 0.0f;
            p1v[o] = s ? p : 0.0f;
        }
    }
    {
        float fl = floorf(pos2);
        #pragma unroll
        for (int o = 0; o < 2; o++) {
            float p = fl + (float)o;
            bool s = (p > 0.0f) && (p < 80.0f);
            w2v[o] = s ? (1.0f - fabsf(pos2 - p)) : 0.0f;
            p2v[o] = s ? p : 0.0f;
        }
    }
    int i0[2] = {(int)p0v[0], (int)p0v[1]};
    int i1[2] = {(int)p1v[0], (int)p1v[1]};
    int i2[2] = {(int)p2v[0], (int)p2v[1]};

    float fv[24];
    #pragma unroll
    for (int t = 0; t < 24; t++) fv[t] = __ldg(ob + (4 + t) * NPIX + r);

    bool zin[2]  = { (i2[0] >= ZAG0) && (i2[0] < ZAG1), (i2[1] >= ZAG0) && (i2[1] < ZAG1) };
    int  zr2[2]  = { i2[0] - ZAG0, i2[1] - ZAG0 };
    bool zadj = (i2[1] == i2[0] + 1) && ((i2[0] & 1) == 0);

    #pragma unroll
    for (int c0 = 0; c0 < 2; c0++)
    #pragma unroll
    for (int c1 = 0; c1 < 2; c1++) {
        float wxy = w0v[c0] * w1v[c1];
        size_t xy = (size_t)((b * VRN + i0[c0]) * VRN + i1[c1]);
        float* base0 = g_vox0 + xy * ZN;
        float* bases = g_voxs + xy * (NQD * ZAGN * 4);
        float wz0 = wxy * w2v[0];
        float wz1 = wxy * w2v[1];

        if (zadj && wz0 > 0.0f && wz1 > 0.0f) {
            asm volatile("red.global.add.v2.f32 [%0], {%1,%2};"
                         :: "l"(base0 + i2[0]), "f"(wz0), "f"(wz1) : "memory");
        } else {
            if (wz0 > 0.0f)
                asm volatile("red.global.add.f32 [%0], %1;"
                             :: "l"(base0 + i2[0]), "f"(wz0) : "memory");
            if (wz1 > 0.0f)
                asm volatile("red.global.add.f32 [%0], %1;"
                             :: "l"(base0 + i2[1]), "f"(wz1) : "memory");
        }

        #pragma unroll
        for (int c2 = 0; c2 < 2; c2++) {
            float w = (c2 == 0) ? wz0 : wz1;
            if (w > 0.0f && zin[c2]) {
                float* dst = bases + zr2[c2] * 4;
                #pragma unroll
                for (int q = 0; q < NQD; q++) {
                    asm volatile("red.global.add.v4.f32 [%0], {%1,%2,%3,%4};"
                                 :: "l"(dst + q * (ZAGN * 4)),
                                    "f"(fv[4*q+0] * w), "f"(fv[4*q+1] * w),
                                    "f"(fv[4*q+2] * w), "f"(fv[4*q+3] * w)
                                 : "memory");
                }
            }
        }
    }
}

// ---------------- proj with exact zero-cell skip ----------------
__global__ void proj_kernel(float* __restrict__ out) {
    int gw   = (blockIdx.x * blockDim.x + threadIdx.x) >> 5;
    int lane = threadIdx.x & 31;
    if (gw >= NXY) return;
    int b    = gw / (VRN * VRN);
    int cell = gw - b * (VRN * VRN);
    int rr = cell / VRN;
    int cc = cell - rr * VRN;

    size_t xy = (size_t)((b * VRN + cc) * VRN + rr);
    const float* base0 = g_vox0 + xy * ZN;

    float sall0 = 0.0f, sag0 = 0.0f;
    #pragma unroll
    for (int z = lane; z < ZN; z += 32) {
        float v0 = rintf(__ldcs(base0 + z));
        sall0 += v0;
        if (z >= ZAG0 && z < ZAG1) sag0 += v0;
    }
    #pragma unroll
    for (int off = 16; off > 0; off >>= 1) {
        sall0 += __shfl_xor_sync(0xffffffffu, sall0, off);
        sag0  += __shfl_xor_sync(0xffffffffu, sag0,  off);
    }

    float4 sag[NQD];
    #pragma unroll
    for (int q = 0; q < NQD; q++) sag[q] = make_float4(0,0,0,0);

    if (sall0 != 0.0f) {
        const float4* bases = (const float4*)(g_voxs + xy * (NQD * ZAGN * 4));
        int zr0 = lane;
        int zr1 = lane + 32;
        #pragma unroll
        for (int q = 0; q < NQD; q++) {
            const float4* qb = bases + q * ZAGN;
            {
                float4 v = __ldcs(qb + zr0);
                sag[q].x += rintf(v.x); sag[q].y += rintf(v.y);
                sag[q].z += rintf(v.z); sag[q].w += rintf(v.w);
            }
            if (zr1 < ZAGN) {
                float4 v = __ldcs(qb + zr1);
                sag[q].x += rintf(v.x); sag[q].y += rintf(v.y);
                sag[q].z += rintf(v.z); sag[q].w += rintf(v.w);
            }
        }
        #pragma unroll
        for (int off = 16; off > 0; off >>= 1) {
            #pragma unroll
            for (int q = 0; q < NQD; q++) {
                sag[q].x += __shfl_xor_sync(0xffffffffu, sag[q].x, off);
                sag[q].y += __shfl_xor_sync(0xffffffffu, sag[q].y, off);
                sag[q].z += __shfl_xor_sync(0xffffffffu, sag[q].z, off);
                sag[q].w += __shfl_xor_sync(0xffffffffu, sag[q].w, off);
            }
        }
    }

    if (lane == 0) {
        float c0 = clip01(sag0);
        float c1 = clip01(sall0);
        out[b * (VRN * VRN) + rr * VRN + cc] = c0;
        if (rr < PROJ_ROWS) {
            float vals[NF];
            vals[0] = c0; vals[1] = c1; vals[2] = 0.0f; vals[3] = 0.0f;
            #pragma unroll
            for (int t = 0; t < 24; t++)
                vals[4 + t] = clip01(getc(sag[t >> 2], t) / 5.0f);
            float4* pr = (float4*)(g_proj + (size_t)((b * PROJ_ROWS + rr) * VRN + cc) * NF);
            #pragma unroll
            for (int q = 0; q < 7; q++)
                pr[q] = make_float4(vals[4*q+0], vals[4*q+1], vals[4*q+2], vals[4*q+3]);
        }
    }
}

// ---------------- kernel A: streaming out = max(maps_last, 0) over the whole map ----------------
// Independent of splat/proj: runs on the side stream concurrent with them.
// Also writes the pose outputs (they only depend on pose inputs).
__global__ void __launch_bounds__(256) stream_max_kernel(const float* __restrict__ maps_last,
                                                         const float* __restrict__ pose_obs,
                                                         const float* __restrict__ poses_last,
                                                         float* __restrict__ out) {
    size_t t = (size_t)blockIdx.x * blockDim.x + threadIdx.x;

    if (t < 12) {   // pose outputs (12 floats, duplicated)
        int bb = (int)t / 3, k = (int)t - bb * 3;
        float ppx = poses_last[bb*3+0], ppy = poses_last[bb*3+1], ppt = poses_last[bb*3+2];
        float dd0 = pose_obs[bb*3+0],  dd1 = pose_obs[bb*3+1],   dd2 = pose_obs[bb*3+2];
        float tth = ppt / R2D_F;
        float ss = sinf(tth), cs = cosf(tth);
        float vy = ppy + dd0 * ss + dd1 * cs;
        float vx = ppx + dd0 * cs - dd1 * ss;
        float vo = ppt + dd2 * R2D_F;
        vo = fmodf(vo - 180.0f, 360.0f) + 180.0f;
        vo = fmodf(vo + 180.0f, 360.0f) - 180.0f;
        float v = (k == 0) ? vx : (k == 1) ? vy : vo;
        out[POSE_OFF + t] = v;
        out[POSE_OFF + 12 + t] = v;
    }

    const size_t n4 = (size_t)MAP_SIZE / 4;
    if (t >= n4) return;
    const float4* src = (const float4*)maps_last;
    float4*       dst = (float4*)(out + FP_SIZE);
    float4 v = src[t];
    v.x = fmaxf(v.x, 0.0f); v.y = fmaxf(v.y, 0.0f);
    v.z = fmaxf(v.z, 0.0f); v.w = fmaxf(v.w, 0.0f);
    dst[t] = v;
}

// ---------------- kernel B: exact rewrite of possibly-tapped pixels ----------------
__global__ void fixup_kernel(const float* __restrict__ maps_last,
                             const float* __restrict__ pose_obs,
                             const float* __restrict__ poses_last,
                             float* __restrict__ out) {
    int t = blockIdx.x * blockDim.x + threadIdx.x;
    if (t >= BSZ * MC2) return;
    int x = t % MC;
    int y = (t / MC) % MC;
    int b = t / MC2;

    float px = poses_last[b*3+0], py = poses_last[b*3+1], pt = poses_last[b*3+2];
    float d0 = pose_obs[b*3+0],  d1 = pose_obs[b*3+1],   d2 = pose_obs[b*3+2];
    float th0 = pt / R2D_F;
    float sth = sinf(th0), cth = cosf(th0);
    float ny = py + d0 * sth + d1 * cth;
    float nx = px + d0 * cth - d1 * sth;
    float no = pt + d2 * R2D_F;
    no = fmodf(no - 180.0f, 360.0f) + 180.0f;
    no = fmodf(no + 180.0f, 360.0f) - 180.0f;

    float sx = -(nx * 100.0f / 5.0f - 240.0f) / 240.0f;
    float sy = -(ny * 100.0f / 5.0f - 240.0f) / 240.0f;
    float tt = (90.0f - no) * DEG2RAD_F;
    float ct = cosf(tt), st = sinf(tt);

    const float S = (float)(2.0 / 479.0);
    float gx = -1.0f + (float)x * S;
    float gy = -1.0f + (float)y * S;

    float ixt = (gx + sx + 1.0f) * 0.5f * 479.0f;
    float iyt = (gy + sy + 1.0f) * 0.5f * 479.0f;

    // conservative per-pixel tap test (validated margins, r14/r15):
    // translate neighbors in [floor(ixt), floor(ixt)+1] x [floor(iyt), floor(iyt)+1];
    // dilate +-1, rotate bbox corners, window +-3 margin.
    {
        float bx0 = floorf(ixt) - 1.0f, bx1 = bx0 + 3.0f;
        float by0 = floorf(iyt) - 1.0f, by1 = by0 + 3.0f;
        float mnx = 1e30f, mxx = -1e30f, mny = 1e30f, mxy = -1e30f;
        #pragma unroll
        for (int cx = 0; cx < 2; cx++)
        #pragma unroll
        for (int cy = 0; cy < 2; cy++) {
            float pxn = (cx == 0) ? bx0 : bx1;
            float pyn = (cy == 0) ? by0 : by1;
            float gxr = -1.0f + pxn * S;
            float gyr = -1.0f + pyn * S;
            float ix2 = ((gxr * ct - gyr * st) + 1.0f) * 0.5f * 479.0f;
            float iy2 = ((gxr * st + gyr * ct) + 1.0f) * 0.5f * 479.0f;
            mnx = fminf(mnx, ix2); mxx = fmaxf(mxx, ix2);
            mny = fminf(mny, iy2); mxy = fmaxf(mxy, iy2);
        }
        bool maybe_tap = (mxx >= 187.0f) && (mnx <= 293.0f) &&
                         (mxy >= 237.0f) && (mny <= 339.0f);
        if (!maybe_tap) return;   // kernel A's max(ml,0) is exact here
    }

    // exact original per-pixel body (r13-proven)
    float x0 = floorf(ixt), y0 = floorf(iyt);
    float wx1 = ixt - x0, wy1 = iyt - y0;
    float wx0 = 1.0f - wx1, wy0 = 1.0f - wy1;

    float nbx[4] = {x0, x0 + 1.0f, x0, x0 + 1.0f};
    float nby[4] = {y0, y0, y0 + 1.0f, y0 + 1.0f};
    float nbw[4] = {wx0 * wy0, wx1 * wy0, wx0 * wy1, wx1 * wy1};

    float4 acc[7];
    #pragma unroll
    for (int q = 0; q < 7; q++) acc[q] = make_float4(0,0,0,0);

    #pragma unroll
    for (int n = 0; n < 4; n++) {
        float pxn = nbx[n], pyn = nby[n];
        if (pxn < 0.0f || pxn > 479.0f || pyn < 0.0f || pyn > 479.0f) continue;
        float W = nbw[n];
        float gxr = -1.0f + pxn * S;
        float gyr = -1.0f + pyn * S;
        float xs2 = gxr * ct - gyr * st;
        float ys2 = gxr * st + gyr * ct;
        float ix2 = (xs2 + 1.0f) * 0.5f * 479.0f;
        float iy2 = (ys2 + 1.0f) * 0.5f * 479.0f;
        float X0 = floorf(ix2), Y0 = floorf(iy2);
        float ux1 = ix2 - X0, uy1 = iy2 - Y0;
        float ux0 = 1.0f - ux1, uy0 = 1.0f - uy1;
        float tx[4] = {X0, X0 + 1.0f, X0, X0 + 1.0f};
        float ty[4] = {Y0, Y0, Y0 + 1.0f, Y0 + 1.0f};
        float tw[4] = {ux0 * uy0, ux1 * uy0, ux0 * uy1, ux1 * uy1};
        #pragma unroll
        for (int k = 0; k < 4; k++) {
            float Xf = tx[k], Yf = ty[k];
            if (Xf >= 190.0f && Xf < 290.0f && Yf >= 240.0f && Yf < 336.0f) {
                int Xi = (int)Xf - 190;
                int Yi = (int)Yf - 240;
                const float4* pr = (const float4*)(g_proj + (size_t)((b * PROJ_ROWS + Yi) * VRN + Xi) * NF);
                float w = W * tw[k];
                #pragma unroll
                for (int q = 0; q < 7; q++) {
                    float4 v = pr[q];
                    acc[q].x = fmaf(w, v.x, acc[q].x);
                    acc[q].y = fmaf(w, v.y, acc[q].y);
                    acc[q].z = fmaf(w, v.z, acc[q].z);
                    acc[q].w = fmaf(w, v.w, acc[q].w);
                }
            }
        }
    }

    size_t base = (size_t)b * CHN * MC2 + (size_t)y * MC + x;
    const float* ml = maps_last + base;
    float* po = out + FP_SIZE + base;
    #pragma unroll
    for (int q = 0; q < 7; q++) {
        po[(size_t)(4*q+0) * MC2] = fmaxf(ml[(size_t)(4*q+0) * MC2], acc[q].x);
        po[(size_t)(4*q+1) * MC2] = fmaxf(ml[(size_t)(4*q+1) * MC2], acc[q].y);
        po[(size_t)(4*q+2) * MC2] = fmaxf(ml[(size_t)(4*q+2) * MC2], acc[q].z);
        po[(size_t)(4*q+3) * MC2] = fmaxf(ml[(size_t)(4*q+3) * MC2], acc[q].w);
    }
}

// ---------------- launch ----------------
// main: splat -> proj -> (wait A) -> B -> (wait zero)
// side: (wait fork) A -> (wait proj) zero
extern "C" void kernel_launch(void* const* d_in, const int* in_sizes, int n_in,
                              void* d_out, int out_size) {
    const float* obs         = (const float*)d_in[0];
    const float* pose_obs    = (const float*)d_in[1];
    const float* maps_last   = (const float*)d_in[2];
    const float* poses_last  = (const float*)d_in[3];
    const float* view_angles = (const float*)d_in[4];
    float* out = (float*)d_out;

    static cudaStream_t s_side = nullptr;
    static cudaEvent_t  e_fork = nullptr, e_A = nullptr, e_proj = nullptr, e_zero = nullptr;
    if (s_side == nullptr) {
        cudaStreamCreateWithFlags(&s_side, cudaStreamNonBlocking);
        cudaEventCreateWithFlags(&e_fork, cudaEventDisableTiming);
        cudaEventCreateWithFlags(&e_A,    cudaEventDisableTiming);
        cudaEventCreateWithFlags(&e_proj, cudaEventDisableTiming);
        cudaEventCreateWithFlags(&e_zero, cudaEventDisableTiming);
    }

    // fork side stream
    cudaEventRecord(e_fork, 0);
    cudaStreamWaitEvent(s_side, e_fork, 0);

    // side: streaming max (independent of splat/proj)
    stream_max_kernel<<<(MAP_SIZE / 4 + 255) / 256, 256, 0, s_side>>>(maps_last, pose_obs, poses_last, out);
    cudaEventRecord(e_A, s_side);

    // main: splat -> proj
    splat_kernel<<<(BSZ * NPIX + 255) / 256, 256>>>(obs, view_angles);
    proj_kernel<<<(NXY * 32 + 255) / 256, 256>>>(out);
    cudaEventRecord(e_proj, 0);

    // side: zero scratch for next launch (after proj has read it)
    cudaStreamWaitEvent(s_side, e_proj, 0);
    zero_vox_kernel<<<2368, 256, 0, s_side>>>();
    cudaEventRecord(e_zero, s_side);

    // main: fixup tapped pixels (needs proj on main, and A's writes)
    cudaStreamWaitEvent(0, e_A, 0);
    fixup_kernel<<<(BSZ * MC2 + 255) / 256, 256>>>(maps_last, pose_obs, poses_last, out);

    // join
    cudaStreamWaitEvent(0, e_zero, 0);
}

// round 17
// speedup vs baseline: 1.0746x; 1.0746x over previous
#include <cuda_runtime.h>
#include <math.h>
#include <stdint.h>

// ---------------- problem constants ----------------
#define BSZ   4
#define CHN   28
#define HH    240
#define WW    320
#define NPIX  (HH*WW)
#define VRN   100
#define ZN    80
#define ZAG0  11
#define ZAG1  49
#define ZAGN  (ZAG1-ZAG0)  // 38
#define NSEG  24
#define NQD   6
#define NF    28
#define MC    480
#define MC2   (MC*MC)
#define PROJ_ROWS 96
#define FP_SIZE  (BSZ*VRN*VRN)
#define MAP_SIZE (BSZ*CHN*MC2)
#define POSE_OFF (FP_SIZE + MAP_SIZE)
#define NXY   (BSZ*VRN*VRN)

#define DEG2RAD_F 0.017453292519943295f
#define R2D_F     57.29577951308232f

// ---------------- scratch ----------------
// Invariant: all-zero at kernel_launch entry. .bss zero at module load; each
// launch re-zeros at its TAIL (overlapped with final_kernel).
__device__ float g_vox0[(size_t)NXY*ZN];                        // 12.8 MB  [xy][z]
__device__ float g_voxs[(size_t)NXY*NQD*ZAGN*4];                // 145.9 MB [xy][q][z][4]
__device__ float g_proj[BSZ*PROJ_ROWS*VRN*NF];                  // 4.3 MB

__device__ __forceinline__ float clip01(float v) { return fminf(fmaxf(v, 0.0f), 1.0f); }

__device__ __forceinline__ float getc(float4 v, int k) {
    switch (k & 3) {
        case 0: return v.x;
        case 1: return v.y;
        case 2: return v.z;
        default: return v.w;
    }
}

// ---------------- zero scratch (TAIL, overlapped with final) ----------------
__global__ void zero_vox_kernel() {
    const size_t n0 = (size_t)NXY*ZN / 4;
    const size_t n1 = (size_t)NXY*NQD*ZAGN*4 / 4;
    size_t i = (size_t)blockIdx.x * blockDim.x + threadIdx.x;
    size_t stride = (size_t)gridDim.x * blockDim.x;
    float4 z4 = make_float4(0.f,0.f,0.f,0.f);
    float4* p0 = (float4*)g_vox0;
    float4* p1 = (float4*)g_voxs;
    for (size_t k = i; k < n0; k += stride) p0[k] = z4;
    for (size_t k = i; k < n1; k += stride) p1[k] = z4;
}

// ---------------- trilinear splat ----------------
__global__ void __launch_bounds__(256) splat_kernel(const float* __restrict__ obs,
                                                    const float* __restrict__ view_angles) {
    int pid = blockIdx.x * blockDim.x + threadIdx.x;
    if (pid >= BSZ * NPIX) return;
    int b = pid / NPIX;
    int r = pid - b * NPIX;
    int i = r / WW;
    int j = r - i * WW;

    const float* ob = obs + (size_t)b * CHN * NPIX;
    float d = __ldg(ob + 3 * NPIX + r);
    if (d < 0.0f) d = 10000.0f;

    const float FOCAL = (float)(160.0 / 0.5773502691896257);
    float X = ((float)j - 159.5f) * d / FOCAL;
    float Z = ((float)(239 - i) - 119.5f) * d / FOCAL;
    float Y = d;

    float a  = view_angles[b] * DEG2RAD_F;
    float ca = cosf(a), sa = sinf(a);
    float Xr = X + 250.0f;
    float Yr = ca * Y - sa * Z;
    float Zr = sa * Y + ca * Z + 155.0f;

    float xn = (Xr / 5.0f - 50.0f) / 100.0f * 2.0f;
    float yn = (Yr / 5.0f - 50.0f) / 100.0f * 2.0f;
    float zn = (Zr / 5.0f - 32.0f) / 80.0f  * 2.0f;
    float pos0 = xn * 50.0f + 50.0f;
    float pos1 = yn * 50.0f + 50.0f;
    float pos2 = zn * 40.0f + 40.0f;

    float p0v[2], w0v[2], p1v[2], w1v[2], p2v[2], w2v[2];
    {
        float fl = floorf(pos0);
        #pragma unroll
        for (int o = 0; o < 2; o++) {
            float p = fl + (float)o;
            bool s = (p > 0.0f) && (p < 100.0f);
            w0v[o] = s ? (1.0f - fabsf(pos0 - p)) : 0.0f;
            p0v[o] = s ? p : 0.0f;
        }
    }
    {
        float fl = floorf(pos1);
        #pragma unroll
        for (int o = 0; o < 2; o++) {
            float p = fl + (float)o;
            bool s = (p > 0.0f) && (p < 100.0f);
            w1v[o] = s ? (1.0f - fabsf(pos1 - p)) : 0.0f;
            p1v[o] = s ? p : 0.0f;
        }
    }
    {
        float fl = floorf(pos2);
        #pragma unroll
        for (int o = 0; o < 2; o++) {
            float p = fl + (float)o;
            bool s = (p > 0.0f) && (p < 80.0f);
            w2v[o] = s ? (1.0f - fabsf(pos2 - p)) : 0.0f;
            p2v[o] = s ? p : 0.0f;
        }
    }
    int i0[2] = {(int)p0v[0], (int)p0v[1]};
    int i1[2] = {(int)p1v[0], (int)p1v[1]};
    int i2[2] = {(int)p2v[0], (int)p2v[1]};

    float fv[24];
    #pragma unroll
    for (int t = 0; t < 24; t++) fv[t] = __ldg(ob + (4 + t) * NPIX + r);

    bool zin[2]  = { (i2[0] >= ZAG0) && (i2[0] < ZAG1), (i2[1] >= ZAG0) && (i2[1] < ZAG1) };
    int  zr2[2]  = { i2[0] - ZAG0, i2[1] - ZAG0 };
    bool zadj = (i2[1] == i2[0] + 1) && ((i2[0] & 1) == 0);

    #pragma unroll
    for (int c0 = 0; c0 < 2; c0++)
    #pragma unroll
    for (int c1 = 0; c1 < 2; c1++) {
        float wxy = w0v[c0] * w1v[c1];
        size_t xy = (size_t)((b * VRN + i0[c0]) * VRN + i1[c1]);
        float* base0 = g_vox0 + xy * ZN;
        float* bases = g_voxs + xy * (NQD * ZAGN * 4);
        float wz0 = wxy * w2v[0];
        float wz1 = wxy * w2v[1];

        if (zadj && wz0 > 0.0f && wz1 > 0.0f) {
            asm volatile("red.global.add.v2.f32 [%0], {%1,%2};"
                         :: "l"(base0 + i2[0]), "f"(wz0), "f"(wz1) : "memory");
        } else {
            if (wz0 > 0.0f)
                asm volatile("red.global.add.f32 [%0], %1;"
                             :: "l"(base0 + i2[0]), "f"(wz0) : "memory");
            if (wz1 > 0.0f)
                asm volatile("red.global.add.f32 [%0], %1;"
                             :: "l"(base0 + i2[1]), "f"(wz1) : "memory");
        }

        #pragma unroll
        for (int c2 = 0; c2 < 2; c2++) {
            float w = (c2 == 0) ? wz0 : wz1;
            if (w > 0.0f && zin[c2]) {
                float* dst = bases + zr2[c2] * 4;
                #pragma unroll
                for (int q = 0; q < NQD; q++) {
                    asm volatile("red.global.add.v4.f32 [%0], {%1,%2,%3,%4};"
                                 :: "l"(dst + q * (ZAGN * 4)),
                                    "f"(fv[4*q+0] * w), "f"(fv[4*q+1] * w),
                                    "f"(fv[4*q+2] * w), "f"(fv[4*q+3] * w)
                                 : "memory");
                }
            }
        }
    }
}

// ---------------- proj with exact agent-window zero-cell skip ----------------
// Invariant chain: seg(xy,z,t) <= count(xy,z) (seg adds w*p with p in [0,1);
// count adds w at the SAME (xy,z)). All values >= 0; rint(x)==0 for 0<=x<=0.5.
// sag0 = sum_{z in [11,49)} rint(count_z) == 0  =>  every windowed count_z <= 0.5
// => every seg voxel <= 0.5 => every rint(seg)==0 => all seg outputs exactly 0.
// (Seg voxels exist ONLY for z in the window, so sag0 — not sall0 — is the
// right predicate; it is ~0 on ~98% of cells.)
__global__ void proj_kernel(float* __restrict__ out) {
    int gw   = (blockIdx.x * blockDim.x + threadIdx.x) >> 5;
    int lane = threadIdx.x & 31;
    if (gw >= NXY) return;
    int b    = gw / (VRN * VRN);
    int cell = gw - b * (VRN * VRN);
    int rr = cell / VRN;
    int cc = cell - rr * VRN;

    size_t xy = (size_t)((b * VRN + cc) * VRN + rr);
    const float* base0 = g_vox0 + xy * ZN;

    float sall0 = 0.0f, sag0 = 0.0f;
    #pragma unroll
    for (int z = lane; z < ZN; z += 32) {
        float v0 = rintf(__ldcs(base0 + z));
        sall0 += v0;
        if (z >= ZAG0 && z < ZAG1) sag0 += v0;
    }
    #pragma unroll
    for (int off = 16; off > 0; off >>= 1) {
        sall0 += __shfl_xor_sync(0xffffffffu, sall0, off);
        sag0  += __shfl_xor_sync(0xffffffffu, sag0,  off);
    }

    float4 sag[NQD];
    #pragma unroll
    for (int q = 0; q < NQD; q++) sag[q] = make_float4(0,0,0,0);

    if (sag0 != 0.0f) {   // warp-uniform; 0 => all seg rints provably 0
        const float4* bases = (const float4*)(g_voxs + xy * (NQD * ZAGN * 4));
        int zr0 = lane;
        int zr1 = lane + 32;
        #pragma unroll
        for (int q = 0; q < NQD; q++) {
            const float4* qb = bases + q * ZAGN;
            {
                float4 v = __ldcs(qb + zr0);
                sag[q].x += rintf(v.x); sag[q].y += rintf(v.y);
                sag[q].z += rintf(v.z); sag[q].w += rintf(v.w);
            }
            if (zr1 < ZAGN) {
                float4 v = __ldcs(qb + zr1);
                sag[q].x += rintf(v.x); sag[q].y += rintf(v.y);
                sag[q].z += rintf(v.z); sag[q].w += rintf(v.w);
            }
        }
        #pragma unroll
        for (int off = 16; off > 0; off >>= 1) {
            #pragma unroll
            for (int q = 0; q < NQD; q++) {
                sag[q].x += __shfl_xor_sync(0xffffffffu, sag[q].x, off);
                sag[q].y += __shfl_xor_sync(0xffffffffu, sag[q].y, off);
                sag[q].z += __shfl_xor_sync(0xffffffffu, sag[q].z, off);
                sag[q].w += __shfl_xor_sync(0xffffffffu, sag[q].w, off);
            }
        }
    }

    if (lane == 0) {
        float c0 = clip01(sag0);
        float c1 = clip01(sall0);
        out[b * (VRN * VRN) + rr * VRN + cc] = c0;
        if (rr < PROJ_ROWS) {
            float vals[NF];
            vals[0] = c0; vals[1] = c1; vals[2] = 0.0f; vals[3] = 0.0f;
            #pragma unroll
            for (int t = 0; t < 24; t++)
                vals[4 + t] = clip01(getc(sag[t >> 2], t) / 5.0f);
            float4* pr = (float4*)(g_proj + (size_t)((b * PROJ_ROWS + rr) * VRN + cc) * NF);
            #pragma unroll
            for (int q = 0; q < 7; q++)
                pr[q] = make_float4(vals[4*q+0], vals[4*q+1], vals[4*q+2], vals[4*q+3]);
        }
    }
}

// ---------------- fused pose + translate(rotate(agent_view)) + max ----------------
__global__ void final_kernel(const float* __restrict__ maps_last,
                             const float* __restrict__ pose_obs,
                             const float* __restrict__ poses_last,
                             float* __restrict__ out) {
    int t = blockIdx.x * blockDim.x + threadIdx.x;
    if (t >= BSZ * MC2) return;
    int x = t % MC;
    int y = (t / MC) % MC;
    int b = t / MC2;

    float px = poses_last[b*3+0], py = poses_last[b*3+1], pt = poses_last[b*3+2];
    float d0 = pose_obs[b*3+0],  d1 = pose_obs[b*3+1],   d2 = pose_obs[b*3+2];
    float th0 = pt / R2D_F;
    float sth = sinf(th0), cth = cosf(th0);
    float ny = py + d0 * sth + d1 * cth;
    float nx = px + d0 * cth - d1 * sth;
    float no = pt + d2 * R2D_F;
    no = fmodf(no - 180.0f, 360.0f) + 180.0f;
    no = fmodf(no + 180.0f, 360.0f) - 180.0f;

    if (t < 12) {
        int bb = t / 3, k = t - bb * 3;
        float ppx = poses_last[bb*3+0], ppy = poses_last[bb*3+1], ppt = poses_last[bb*3+2];
        float dd0 = pose_obs[bb*3+0],  dd1 = pose_obs[bb*3+1],   dd2 = pose_obs[bb*3+2];
        float tth = ppt / R2D_F;
        float ss = sinf(tth), cs = cosf(tth);
        float vy = ppy + dd0 * ss + dd1 * cs;
        float vx = ppx + dd0 * cs - dd1 * ss;
        float vo = ppt + dd2 * R2D_F;
        vo = fmodf(vo - 180.0f, 360.0f) + 180.0f;
        vo = fmodf(vo + 180.0f, 360.0f) - 180.0f;
        float v = (k == 0) ? vx : (k == 1) ? vy : vo;
        out[POSE_OFF + t] = v;
        out[POSE_OFF + 12 + t] = v;
    }

    float sx = -(nx * 100.0f / 5.0f - 240.0f) / 240.0f;
    float sy = -(ny * 100.0f / 5.0f - 240.0f) / 240.0f;
    float tt = (90.0f - no) * DEG2RAD_F;
    float ct = cosf(tt), st = sinf(tt);

    const float S = (float)(2.0 / 479.0);
    float gx = -1.0f + (float)x * S;
    float gy = -1.0f + (float)y * S;

    float ixt = (gx + sx + 1.0f) * 0.5f * 479.0f;
    float iyt = (gy + sy + 1.0f) * 0.5f * 479.0f;
    float x0 = floorf(ixt), y0 = floorf(iyt);
    float wx1 = ixt - x0, wy1 = iyt - y0;
    float wx0 = 1.0f - wx1, wy0 = 1.0f - wy1;

    float nbx[4] = {x0, x0 + 1.0f, x0, x0 + 1.0f};
    float nby[4] = {y0, y0, y0 + 1.0f, y0 + 1.0f};
    float nbw[4] = {wx0 * wy0, wx1 * wy0, wx0 * wy1, wx1 * wy1};

    float4 acc[7];
    #pragma unroll
    for (int q = 0; q < 7; q++) acc[q] = make_float4(0,0,0,0);

    #pragma unroll
    for (int n = 0; n < 4; n++) {
        float pxn = nbx[n], pyn = nby[n];
        if (pxn < 0.0f || pxn > 479.0f || pyn < 0.0f || pyn > 479.0f) continue;
        float W = nbw[n];
        float gxr = -1.0f + pxn * S;
        float gyr = -1.0f + pyn * S;
        float xs2 = gxr * ct - gyr * st;
        float ys2 = gxr * st + gyr * ct;
        float ix2 = (xs2 + 1.0f) * 0.5f * 479.0f;
        float iy2 = (ys2 + 1.0f) * 0.5f * 479.0f;
        float X0 = floorf(ix2), Y0 = floorf(iy2);
        float ux1 = ix2 - X0, uy1 = iy2 - Y0;
        float ux0 = 1.0f - ux1, uy0 = 1.0f - uy1;
        float tx[4] = {X0, X0 + 1.0f, X0, X0 + 1.0f};
        float ty[4] = {Y0, Y0, Y0 + 1.0f, Y0 + 1.0f};
        float tw[4] = {ux0 * uy0, ux1 * uy0, ux0 * uy1, ux1 * uy1};
        #pragma unroll
        for (int k = 0; k < 4; k++) {
            float Xf = tx[k], Yf = ty[k];
            if (Xf >= 190.0f && Xf < 290.0f && Yf >= 240.0f && Yf < 336.0f) {
                int Xi = (int)Xf - 190;
                int Yi = (int)Yf - 240;
                const float4* pr = (const float4*)(g_proj + (size_t)((b * PROJ_ROWS + Yi) * VRN + Xi) * NF);
                float w = W * tw[k];
                #pragma unroll
                for (int q = 0; q < 7; q++) {
                    float4 v = pr[q];
                    acc[q].x = fmaf(w, v.x, acc[q].x);
                    acc[q].y = fmaf(w, v.y, acc[q].y);
                    acc[q].z = fmaf(w, v.z, acc[q].z);
                    acc[q].w = fmaf(w, v.w, acc[q].w);
                }
            }
        }
    }

    size_t base = (size_t)b * CHN * MC2 + (size_t)y * MC + x;
    const float* ml = maps_last + base;
    float* po = out + FP_SIZE + base;
    #pragma unroll
    for (int q = 0; q < 7; q++) {
        po[(size_t)(4*q+0) * MC2] = fmaxf(ml[(size_t)(4*q+0) * MC2], acc[q].x);
        po[(size_t)(4*q+1) * MC2] = fmaxf(ml[(size_t)(4*q+1) * MC2], acc[q].y);
        po[(size_t)(4*q+2) * MC2] = fmaxf(ml[(size_t)(4*q+2) * MC2], acc[q].z);
        po[(size_t)(4*q+3) * MC2] = fmaxf(ml[(size_t)(4*q+3) * MC2], acc[q].w);
    }
}

// ---------------- launch ----------------
// Order: splat -> proj -> { final (main) || zero (side) } -> join.  (r13-proven)
extern "C" void kernel_launch(void* const* d_in, const int* in_sizes, int n_in,
                              void* d_out, int out_size) {
    const float* obs         = (const float*)d_in[0];
    const float* pose_obs    = (const float*)d_in[1];
    const float* maps_last   = (const float*)d_in[2];
    const float* poses_last  = (const float*)d_in[3];
    const float* view_angles = (const float*)d_in[4];
    float* out = (float*)d_out;

    static cudaStream_t s_side = nullptr;
    static cudaEvent_t  e_fork = nullptr, e_join = nullptr;
    if (s_side == nullptr) {
        cudaStreamCreateWithFlags(&s_side, cudaStreamNonBlocking);
        cudaEventCreateWithFlags(&e_fork, cudaEventDisableTiming);
        cudaEventCreateWithFlags(&e_join, cudaEventDisableTiming);
    }

    splat_kernel<<<(BSZ * NPIX + 255) / 256, 256>>>(obs, view_angles);
    proj_kernel<<<(NXY * 32 + 255) / 256, 256>>>(out);

    cudaEventRecord(e_fork, 0);
    cudaStreamWaitEvent(s_side, e_fork, 0);
    zero_vox_kernel<<<2368, 256, 0, s_side>>>();

    final_kernel<<<(BSZ * MC2 + 255) / 256, 256>>>(maps_last, pose_obs, poses_last, out);

    cudaEventRecord(e_join, s_side);
    cudaStreamWaitEvent(0, e_join, 0);
}